// round 14
// baseline (speedup 1.0000x reference)
#include <cuda_runtime.h>
#include <cuda_bf16.h>

// BoundaryLoss: mean(sigmoid(logits) * EDT2D(target)), [8,1,256,256].
//
// Stage 1 (k_rowdist): warp-per-row exact 1D row distance^2 (shuffle scans).
// Stage 2 (k_edt_loss): CTA = 32-row x 32-px tile (512 CTAs, 4096 warps).
//   dr2 strip (40 rows x 8 float4, +-4 halo) staged coalesced into 5KB smem
//   (1.25 LDG/thread instead of 9). Window min over smem (LDS.128, 29cyc)
//   + rare exact global tail; fused sigmoid; block reduce + 1 atomicAdd.

#define B 8
#define H 256
#define W 256
#define NPIX (B * H * W)          // 524288
#define BIGD 1000000.0f
#define FULL 0xffffffffu
#define RW4 (W / 4)               // 64 float4 per row

__device__ float g_dr2[NPIX];     // squared 1D row distances

__global__ void k_rowdist(const int* __restrict__ target,
                          float* __restrict__ out)
{
    if (blockIdx.x == 0 && threadIdx.x == 0) *out = 0.0f;

    const int lane = threadIdx.x & 31;
    const int warp = threadIdx.x >> 5;
    const int row  = (blockIdx.x << 3) + warp;     // 8 rows per block
    const int base = row * W;
    const int w0   = lane << 3;                    // 8 px per lane

    const int4* tp = reinterpret_cast<const int4*>(target + base + w0);
    const int4 t0 = tp[0];
    const int4 t1 = tp[1];
    int fg[8];
    fg[0] = t0.x > 0; fg[1] = t0.y > 0; fg[2] = t0.z > 0; fg[3] = t0.w > 0;
    fg[4] = t1.x > 0; fg[5] = t1.y > 0; fg[6] = t1.z > 0; fg[7] = t1.w > 0;

    // nearest fg <= w : prefix max of (fg? w : -1)
    int pl[8];
    int run = -1;
#pragma unroll
    for (int k = 0; k < 8; ++k) {
        const int cand = fg[k] ? (w0 + k) : -1;
        run = max(run, cand);
        pl[k] = run;
    }
    int x = run;
#pragma unroll
    for (int off = 1; off < 32; off <<= 1) {
        const int y = __shfl_up_sync(FULL, x, off);
        if (lane >= off) x = max(x, y);
    }
    int exl = __shfl_up_sync(FULL, x, 1);
    if (lane == 0) exl = -1;

    // nearest fg >= w : suffix min of (fg? w : 512)
    int pr[8];
    int run2 = 512;
#pragma unroll
    for (int k = 7; k >= 0; --k) {
        const int cand = fg[k] ? (w0 + k) : 512;
        run2 = min(run2, cand);
        pr[k] = run2;
    }
    int x2 = run2;
#pragma unroll
    for (int off = 1; off < 32; off <<= 1) {
        const int y = __shfl_down_sync(FULL, x2, off);
        if (lane + off < 32) x2 = min(x2, y);
    }
    int exr = __shfl_down_sync(FULL, x2, 1);
    if (lane == 31) exr = 512;

    float o[8];
#pragma unroll
    for (int k = 0; k < 8; ++k) {
        const int L = max(pl[k], exl);
        const int R = min(pr[k], exr);
        const float dl = (L >= 0)  ? (float)(w0 + k - L) : BIGD;
        const float dr = (R < 512) ? (float)(R - (w0 + k)) : BIGD;
        const float d  = fminf(dl, dr);
        o[k] = d * d;
    }
    float4* op = reinterpret_cast<float4*>(g_dr2 + base + w0);
    op[0] = make_float4(o[0], o[1], o[2], o[3]);
    op[1] = make_float4(o[4], o[5], o[6], o[7]);
}

__device__ __forceinline__ float4 fmin4a(float4 a, float4 bu, float4 bd, float rr)
{
    a.x = fminf(a.x, fminf(bu.x, bd.x) + rr);
    a.y = fminf(a.y, fminf(bu.y, bd.y) + rr);
    a.z = fminf(a.z, fminf(bu.z, bd.z) + rr);
    a.w = fminf(a.w, fminf(bu.w, bd.w) + rr);
    return a;
}

__global__ __launch_bounds__(256)
void k_edt_loss(const float* __restrict__ logits,
                float* __restrict__ out)
{
    __shared__ float4 s[40][8];        // 5 KB: 40 rows x 32 px of dr2

    const int tid = threadIdx.x;
    const int c   = blockIdx.x;        // 512 CTAs
    const int b   = c >> 6;            // image
    const int rem = c & 63;
    const int i0  = (rem >> 3) * 32;   // first output row of tile
    const int cf0 = (rem & 7) * 8;     // first float4 column of tile

    const float4* dr  = reinterpret_cast<const float4*>(g_dr2);
    const float4  big = make_float4(BIGD, BIGD, BIGD, BIGD);

    // ---- stage strip: rows i0-4 .. i0+35, cols cf0..cf0+7 (coalesced) ----
    {
        const int rl = tid >> 3;               // 0..31
        const int cl = tid & 7;
        const int gi = i0 - 4 + rl;
        s[rl][cl] = (gi >= 0 && gi < H) ? dr[(b * H + gi) * RW4 + cf0 + cl] : big;
    }
    if (tid < 64) {
        const int rl = 32 + (tid >> 3);        // 32..39
        const int cl = tid & 7;
        const int gi = i0 - 4 + rl;            // >= 28, may exceed H-1
        s[rl][cl] = (gi < H) ? dr[(b * H + gi) * RW4 + cf0 + cl] : big;
    }
    __syncthreads();

    // ---- window min from smem ----
    const int orow = tid >> 3;                 // 0..31
    const int ocol = tid & 7;                  // 0..7
    const int i    = i0 + orow;

    float4 cur = s[orow + 4][ocol];
#pragma unroll
    for (int r = 1; r <= 4; ++r) {
        const float rr = (float)(r * r);
        cur = fmin4a(cur, s[orow + 4 - r][ocol], s[orow + 4 + r][ocol], rr);
    }

    // rare exact tail: r >= 5, global reads, scalar per component
    if (fmaxf(fmaxf(cur.x, cur.y), fmaxf(cur.z, cur.w)) > 25.0f) {
        float* cc = &cur.x;
        const int p0 = (b * H + i) * W + (cf0 + ocol) * 4;
#pragma unroll
        for (int q = 0; q < 4; ++q) {
            for (int r = 5; r < H && (float)(r * r) < cc[q]; ++r) {
                const float rr = (float)(r * r);
                if (i >= r)    cc[q] = fminf(cc[q], g_dr2[p0 + q - (r << 8)] + rr);
                if (i + r < H) cc[q] = fminf(cc[q], g_dr2[p0 + q + (r << 8)] + rr);
            }
        }
    }

    // ---- loss: sigmoid(logits) * sqrt(D2) ----
    const float4 xv =
        reinterpret_cast<const float4*>(logits)[(b * H + i) * RW4 + cf0 + ocol];
    const float px = 1.0f / (1.0f + __expf(-xv.x));
    const float py = 1.0f / (1.0f + __expf(-xv.y));
    const float pz = 1.0f / (1.0f + __expf(-xv.z));
    const float pw = 1.0f / (1.0f + __expf(-xv.w));

    float val = px * sqrtf(cur.x) + py * sqrtf(cur.y)
              + pz * sqrtf(cur.z) + pw * sqrtf(cur.w);
    val *= (1.0f / (float)NPIX);

    // block reduction -> one atomic per CTA
#pragma unroll
    for (int o = 16; o; o >>= 1)
        val += __shfl_xor_sync(FULL, val, o);

    __shared__ float ws[8];
    if ((tid & 31) == 0) ws[tid >> 5] = val;
    __syncthreads();
    if (tid == 0) {
        float t = ws[0];
#pragma unroll
        for (int k = 1; k < 8; ++k) t += ws[k];
        atomicAdd(out, t);
    }
}

extern "C" void kernel_launch(void* const* d_in, const int* in_sizes, int n_in,
                              void* d_out, int out_size)
{
    const float* logits = (const float*)d_in[0];
    const int*   target = (const int*)d_in[1];
    float*       out    = (float*)d_out;

    k_rowdist<<<(B * H) / 8, 256>>>(target, out);
    k_edt_loss<<<B * 64, 256>>>(logits, out);
}